// round 11
// baseline (speedup 1.0000x reference)
#include <cuda_runtime.h>
#include <math.h>

// ---------------- problem geometry ----------------
#define LTOT 28928          // tokens per batch across seqs 0..3
#define BTOK 231424         // 8 * LTOT
#define TOTC 452            // chunks (T=64) per batch: 341+85+21+5
#define NB   8

// ---------------- static device scratch ----------------
__device__ __align__(16) float g_xz[32][BTOK]; // in-proj output: xi (0..15), z (16..31)
__device__ __align__(16) float g_P[NB*TOTC*256];  // per-chunk product of a
__device__ __align__(16) float g_S[NB*TOTC*256];  // per-chunk local scan end
__device__ __align__(16) float g_I[NB*TOTC*256];  // per-chunk inclusive prefix
__device__ int g_flag[NB*TOTC];                   // 0=none 1=aggregate 2=inclusive

__constant__ int c_plen[5]  = {16384,4096,1024,256,64};      // spatial size per tensor (= ch stride)
__constant__ int c_bs[5]    = {131072,65536,24576,8192,3072};// batch stride per tensor
__constant__ int c_obase[5] = {0,1048576,1572864,1769472,1835008};
__constant__ int c_O[4]     = {0,21824,27264,28608};         // seq offsets within a batch
__constant__ int c_CB[4]    = {0,341,426,447};               // chunk base per seq

__device__ __forceinline__ float siluf(float x){ return x * (1.0f/(1.0f+__expf(-x))); }
__device__ __forceinline__ float softplusf(float x){ return (x>20.0f)? x : log1pf(__expf(x)); }

// ---------------- K1: gather + in-projection ----------------
__global__ void k1_gather(const float* __restrict__ t1, const float* __restrict__ t2,
                          const float* __restrict__ t3, const float* __restrict__ t4,
                          const float* __restrict__ t5, const float* __restrict__ in_w){
  __shared__ float s_w[256]; // (32,8)
  int tid = threadIdx.x;
  if (tid < 256) s_w[tid] = in_w[tid];
  __syncthreads();
  int tg = blockIdx.x*256 + tid;           // < BTOK exactly (904 blocks)
  int b = tg / LTOT, r = tg % LTOT;
  int s = (r>=21824)+(r>=27264)+(r>=28608);
  int p = r - c_O[s];
  int i = s, pp = p;
  while (pp >= c_plen[i]) { pp -= c_plen[i]; ++i; }
  const float* tp = (i==0)?t1:(i==1)?t2:(i==2)?t3:(i==3)?t4:t5;
  int base = b*c_bs[i] + (8*s)*c_plen[i] + pp;
  float x[8];
  #pragma unroll
  for (int c=0;c<8;c++) x[c] = tp[base + c*c_plen[i]];
  #pragma unroll
  for (int j=0;j<32;j++){
    float v = 0.f;
    #pragma unroll
    for (int c=0;c<8;c++) v += x[c]*s_w[j*8+c];
    g_xz[j][tg] = v;
  }
}

// ======= shared record recompute (one per chunk, fused kernel) ============
struct alignas(16) RecSmem {
  float  xi[16][68];      // reused as y[16][68] after conv phase
  float  xcs[16][68];
  float2 dldu[16][65];    // {delta, delta*xc}
  float2 BC[16][65];      // {B, C}
  float  dtv[64];
  float  xp[564];         // 33 rows, stride 17
  float  cw[64], cb[16], dtw[16], dtb[16];
  float  pad[4];
};

__device__ __forceinline__ void rec_compute(RecSmem& S, int tid, int tb, int cis,
    const float* __restrict__ xproj_w, const float* __restrict__ conv_w,
    const float* __restrict__ conv_b,  const float* __restrict__ dt_w,
    const float* __restrict__ dt_b){
  for (int i=tid;i<528;i+=256){ int row=i>>4, col=i&15; S.xp[row*17+col]=xproj_w[i]; }
  if (tid<64) S.cw[tid]=conv_w[tid];
  if (tid<16){ S.cb[tid]=conv_b[tid]; S.dtw[tid]=dt_w[tid]; S.dtb[tid]=dt_b[tid]; }
  for (int i=tid;i<272;i+=256){
    int d=i/17, q=i%17;
    float4 v;
    if (cis==0 && q==0) v = make_float4(0.f,0.f,0.f,0.f);
    else v = *reinterpret_cast<const float4*>(&g_xz[d][tb-4+q*4]);
    S.xi[d][q*4+0]=v.x; S.xi[d][q*4+1]=v.y; S.xi[d][q*4+2]=v.z; S.xi[d][q*4+3]=v.w;
  }
  __syncthreads();
  #pragma unroll
  for (int k=0;k<4;k++){
    int idx = tid + k*256;
    int d = idx>>6, t = idx&63;
    float acc = S.cb[d];
    #pragma unroll
    for (int kk=0;kk<4;kk++) acc += S.cw[d*4+kk]*S.xi[d][t+1+kk];
    S.xcs[d][t] = siluf(acc);
  }
  __syncthreads();
  if (tid<64){
    float v=0.f;
    #pragma unroll
    for (int d=0;d<16;d++) v += S.xcs[d][tid]*S.xp[d];
    S.dtv[tid]=v;
  }
  __syncthreads();
  {
    int j = tid & 15;
    int t0 = (tid >> 4) << 2;
    float aB0=0.f,aB1=0.f,aB2=0.f,aB3=0.f;
    float aC0=0.f,aC1=0.f,aC2=0.f,aC3=0.f;
    #pragma unroll
    for (int d=0;d<16;d++){
      float4 x4 = *reinterpret_cast<const float4*>(&S.xcs[d][t0]);
      float wb = S.xp[(1+j)*17+d];
      float wc = S.xp[(17+j)*17+d];
      aB0 += x4.x*wb; aB1 += x4.y*wb; aB2 += x4.z*wb; aB3 += x4.w*wb;
      aC0 += x4.x*wc; aC1 += x4.y*wc; aC2 += x4.z*wc; aC3 += x4.w*wc;
    }
    S.BC[j][t0+0] = make_float2(aB0, aC0);
    S.BC[j][t0+1] = make_float2(aB1, aC1);
    S.BC[j][t0+2] = make_float2(aB2, aC2);
    S.BC[j][t0+3] = make_float2(aB3, aC3);
  }
  #pragma unroll
  for (int k=0;k<4;k++){
    int idx = tid + k*256;
    int d = idx>>6, t = idx&63;
    float del = softplusf(S.dtv[t]*S.dtw[d]+S.dtb[d]);
    S.dldu[d][t] = make_float2(del, del*S.xcs[d][t]);
  }
  __syncthreads();
}

// ---------------- K35: single-pass fused scan (decoupled look-back) -------
struct alignas(16) K35Smem {
  RecSmem R;
  float ow[128], pwm[64], pbv[8], gv[8], nbvv[8], Dvv[16];
  float skip; float pad3[3];
};

__global__ void k35_fused(const float* __restrict__ t1, const float* __restrict__ t2,
                          const float* __restrict__ t3, const float* __restrict__ t4,
                          const float* __restrict__ t5,
                          const float* __restrict__ xproj_w, const float* __restrict__ conv_w,
                          const float* __restrict__ conv_b, const float* __restrict__ dt_w,
                          const float* __restrict__ dt_b, const float* __restrict__ Alog,
                          const float* __restrict__ out_w, const float* __restrict__ Dv,
                          const float* __restrict__ ng_, const float* __restrict__ nbv,
                          const float* __restrict__ pw, const float* __restrict__ pb,
                          const float* __restrict__ skipp, float* __restrict__ out){
  __shared__ K35Smem S;
  int blk = blockIdx.x;
  int b = blk / TOTC, cg = blk % TOTC;
  int s = (cg>=341)+(cg>=426)+(cg>=447);
  int cis = cg - c_CB[s];
  int tb = b*LTOT + c_O[s] + cis*64;
  int tid = threadIdx.x;
  // block-uniform tensor mapping (chunk lies entirely inside one tensor)
  int ti = s, pp = cis*64;
  while (pp >= c_plen[ti]) { pp -= c_plen[ti]; ++ti; }
  const float* tp = (ti==0)?t1:(ti==1)?t2:(ti==2)?t3:(ti==3)?t4:t5;
  int ibase = b*c_bs[ti] + (8*s)*c_plen[ti] + pp;
  // epilogue params (disjoint smem; ordered by rec_compute barriers)
  if (tid<128) S.ow[tid]=out_w[tid];
  else {
    int u = tid-128;
    if (u<64) S.pwm[u]=pw[u];
    else if (u<72) S.pbv[u-64]=pb[u-64];
    else if (u<80) S.gv[u-72]=ng_[u-72];
    else if (u<88) S.nbvv[u-80]=nbv[u-80];
    else if (u<104) S.Dvv[u-88]=Dv[u-88];
    else if (u==104) S.skip = skipp[0];
  }
  rec_compute(S.R, tid, tb, cis, xproj_w, conv_w, conv_b, dt_w, dt_b);

  int cidx = blk;
  int d = tid>>2, ngi = tid&3;
  float ac0=0,ac1=0,ac2=0,ac3=0;
  float P0=1,P1=1,P2=1,P3=1, A0=0,A1=0,A2=0,A3=0;
  float h0=0,h1=0,h2=0,h3=0;
  int soff = (tid>>2)*16 + 4*(tid&3);
  // ---- phase A: local (P,S) ----
  if (tid < 64){
    float4 al = *reinterpret_cast<const float4*>(&Alog[d*16 + 4*ngi]);
    const float L2E = 1.4426950408889634f;
    ac0=-__expf(al.x)*L2E; ac1=-__expf(al.y)*L2E;
    ac2=-__expf(al.z)*L2E; ac3=-__expf(al.w)*L2E;
    #pragma unroll 4
    for (int t=0;t<64;t++){
      float2 du = S.R.dldu[d][t];
      float b0 = S.R.BC[4*ngi+0][t].x;
      float b1 = S.R.BC[4*ngi+1][t].x;
      float b2 = S.R.BC[4*ngi+2][t].x;
      float b3 = S.R.BC[4*ngi+3][t].x;
      float a0=exp2f(du.x*ac0), a1=exp2f(du.x*ac1),
            a2=exp2f(du.x*ac2), a3=exp2f(du.x*ac3);
      A0 = a0*A0 + du.y*b0;  P0 *= a0;
      A1 = a1*A1 + du.y*b1;  P1 *= a1;
      A2 = a2*A2 + du.y*b2;  P2 *= a2;
      A3 = a3*A3 + du.y*b3;  P3 *= a3;
    }
    int off = cidx*256 + soff;
    *reinterpret_cast<float4*>(&g_P[off]) = make_float4(P0,P1,P2,P3);
    *reinterpret_cast<float4*>(&g_S[off]) = make_float4(A0,A1,A2,A3);
    __threadfence();
  }
  __syncthreads();
  if (tid==0) atomicExch(&g_flag[cidx], 1);
  // ---- look-back: compute exclusive prefix h_start ----
  if (tid < 64){
    float aS0=0,aS1=0,aS2=0,aS3=0;
    float aP0=1,aP1=1,aP2=1,aP3=1;
    int back = 1;
    while (cis - back >= 0){
      int pidx = cidx - back;
      int st = 0;
      if ((tid&31)==0){
        while ((st = atomicAdd(&g_flag[pidx], 0)) == 0) __nanosleep(64);
      }
      st = __shfl_sync(0xffffffffu, st, 0);
      __threadfence();
      int off = pidx*256 + soff;
      if (st == 2){
        float4 I = *reinterpret_cast<const float4*>(&g_I[off]);
        aS0 += aP0*I.x; aS1 += aP1*I.y; aS2 += aP2*I.z; aS3 += aP3*I.w;
        break;
      } else {
        float4 Sp = *reinterpret_cast<const float4*>(&g_S[off]);
        float4 Pp = *reinterpret_cast<const float4*>(&g_P[off]);
        aS0 += aP0*Sp.x; aS1 += aP1*Sp.y; aS2 += aP2*Sp.z; aS3 += aP3*Sp.w;
        aP0 *= Pp.x; aP1 *= Pp.y; aP2 *= Pp.z; aP3 *= Pp.w;
        back++;
      }
    }
    h0=aS0; h1=aS1; h2=aS2; h3=aS3;
    int off = cidx*256 + soff;
    *reinterpret_cast<float4*>(&g_I[off]) =
        make_float4(P0*h0+A0, P1*h1+A1, P2*h2+A2, P3*h3+A3);
    __threadfence();
  }
  __syncthreads();
  if (tid==0) atomicExch(&g_flag[cidx], 2);
  // ---- phase C: replay with h_start, reduce y ----
  float (*ysh)[68] = reinterpret_cast<float (*)[68]>(S.R.xi);  // xi dead after conv
  if (tid < 64){
    #pragma unroll 4
    for (int t=0;t<64;t++){
      float2 du = S.R.dldu[d][t];
      float2 bc0 = S.R.BC[4*ngi+0][t];
      float2 bc1 = S.R.BC[4*ngi+1][t];
      float2 bc2 = S.R.BC[4*ngi+2][t];
      float2 bc3 = S.R.BC[4*ngi+3][t];
      float a0=exp2f(du.x*ac0), a1=exp2f(du.x*ac1),
            a2=exp2f(du.x*ac2), a3=exp2f(du.x*ac3);
      h0 = a0*h0 + du.y*bc0.x;
      h1 = a1*h1 + du.y*bc1.x;
      h2 = a2*h2 + du.y*bc2.x;
      h3 = a3*h3 + du.y*bc3.x;
      float pr = h0*bc0.y + h1*bc1.y + h2*bc2.y + h3*bc3.y;
      pr += __shfl_xor_sync(0xffffffffu, pr, 1);
      pr += __shfl_xor_sync(0xffffffffu, pr, 2);
      if (ngi==0) ysh[d][t]=pr;
    }
  }
  __syncthreads();
  // ---- epilogue + scatter (z and x8 read directly, coalesced over t) ----
  if (tid < 64){
    int t = tid;
    float yf[16];
    #pragma unroll
    for (int dd=0;dd<16;dd++){
      float z = g_xz[16+dd][tb+t];
      yf[dd] = (ysh[dd][t] + S.R.xcs[dd][t]*S.Dvv[dd]) * siluf(z);
    }
    float o[8]; float mu=0.f;
    #pragma unroll
    for (int ch=0;ch<8;ch++){
      float acc = S.skip * tp[ibase + ch*c_plen[ti] + t];
      #pragma unroll
      for (int dd=0;dd<16;dd++) acc += yf[dd]*S.ow[ch*16+dd];
      o[ch]=acc; mu+=acc;
    }
    mu *= 0.125f;
    float var=0.f;
    #pragma unroll
    for (int ch=0;ch<8;ch++){ float dv=o[ch]-mu; var += dv*dv; }
    var *= 0.125f;
    float rs = rsqrtf(var + 1e-5f);
    float ln[8];
    #pragma unroll
    for (int ch=0;ch<8;ch++) ln[ch] = (o[ch]-mu)*rs*S.gv[ch] + S.nbvv[ch];
    int base = c_obase[ti] + ibase + t;
    #pragma unroll
    for (int j=0;j<8;j++){
      float acc = S.pbv[j];
      #pragma unroll
      for (int ch=0;ch<8;ch++) acc += ln[ch]*S.pwm[j*8+ch];
      out[base + j*c_plen[ti]] = acc;
    }
  }
}

// ---------------- K6: whole m1 path (c5, L=64, dm=16) in one kernel ----------------
__global__ void k6_m1(const float* __restrict__ t5, const float* __restrict__ in_w,
                      const float* __restrict__ conv_w, const float* __restrict__ conv_b,
                      const float* __restrict__ xproj_w, const float* __restrict__ dt_w,
                      const float* __restrict__ dt_b, const float* __restrict__ Alog,
                      const float* __restrict__ Dv, const float* __restrict__ out_w,
                      const float* __restrict__ ng, const float* __restrict__ nbv,
                      const float* __restrict__ pw, const float* __restrict__ pb,
                      const float* __restrict__ skipp, float* __restrict__ out){
  __shared__ float s_x[64][16];
  __shared__ float s_xi[64][32];
  __shared__ float s_z[64][32];
  __shared__ float s_xc[64][32];
  __shared__ float s_B[64][16];
  __shared__ float s_C[64][16];
  __shared__ float s_dt[64];
  __shared__ float s_y[64][32];
  int b = blockIdx.x, tid = threadIdx.x;
  for (int i=tid;i<64*16;i+=512){
    int t=i>>4, c=i&15;
    s_x[t][c] = t5[b*3072 + (32+c)*64 + t];
  }
  __syncthreads();
  for (int i=tid;i<64*64;i+=512){
    int t=i>>6, j=i&63;
    float v=0.f;
    #pragma unroll
    for (int c=0;c<16;c++) v += s_x[t][c]*in_w[j*16+c];
    if (j<32) s_xi[t][j]=v; else s_z[t][j-32]=v;
  }
  __syncthreads();
  for (int i=tid;i<64*32;i+=512){
    int t=i>>5, d=i&31;
    float acc = conv_b[d];
    #pragma unroll
    for (int k=0;k<4;k++){
      int tt = t-3+k;
      if (tt>=0) acc += conv_w[d*4+k]*s_xi[tt][d];
    }
    s_xc[t][d] = siluf(acc);
  }
  __syncthreads();
  for (int i=tid;i<64*33;i+=512){
    int t=i/33, j=i%33;
    float v=0.f;
    #pragma unroll
    for (int d=0;d<32;d++) v += s_xc[t][d]*xproj_w[j*32+d];
    if (j==0) s_dt[t]=v;
    else if (j<17) s_B[t][j-1]=v;
    else s_C[t][j-17]=v;
  }
  __syncthreads();
  for (int i=tid;i<64*32;i+=512){
    int t=i>>5, d=i&31;
    s_xi[t][d] = softplusf(s_dt[t]*dt_w[d] + dt_b[d]);
  }
  __syncthreads();
  {
    int d=tid>>4, n=tid&15;
    float ac = -__expf(Alog[d*16+n])*1.4426950408889634f;
    float h=0.f;
    for (int t=0;t<64;t++){
      float dl = s_xi[t][d];
      float a = exp2f(dl*ac);
      h = a*h + dl*s_xc[t][d]*s_B[t][n];
      float pr = h*s_C[t][n];
      pr += __shfl_xor_sync(0xffffffffu, pr, 8);
      pr += __shfl_xor_sync(0xffffffffu, pr, 4);
      pr += __shfl_xor_sync(0xffffffffu, pr, 2);
      pr += __shfl_xor_sync(0xffffffffu, pr, 1);
      if (n==0) s_y[t][d]=pr;
    }
  }
  __syncthreads();
  if (tid<64){
    int t=tid;
    float skip = skipp[0];
    float yf[32];
    #pragma unroll
    for (int d=0;d<32;d++) yf[d] = (s_y[t][d] + s_xc[t][d]*Dv[d]) * siluf(s_z[t][d]);
    float o[16]; float mu=0.f;
    #pragma unroll
    for (int ch=0;ch<16;ch++){
      float acc = skip * s_x[t][ch];
      #pragma unroll
      for (int d=0;d<32;d++) acc += yf[d]*out_w[ch*32+d];
      o[ch]=acc; mu+=acc;
    }
    mu *= (1.0f/16.0f);
    float var=0.f;
    #pragma unroll
    for (int ch=0;ch<16;ch++){ float dv=o[ch]-mu; var+=dv*dv; }
    var *= (1.0f/16.0f);
    float rs = rsqrtf(var+1e-5f);
    float ln[16];
    #pragma unroll
    for (int ch=0;ch<16;ch++) ln[ch] = (o[ch]-mu)*rs*ng[ch]+nbv[ch];
    #pragma unroll
    for (int j=0;j<16;j++){
      float acc = pb[j];
      #pragma unroll
      for (int ch=0;ch<16;ch++) acc += ln[ch]*pw[j*16+ch];
      out[1835008 + b*3072 + (32+j)*64 + t] = acc;
    }
  }
}

// ---------------- launch ----------------
extern "C" void kernel_launch(void* const* d_in, const int* in_sizes, int n_in,
                              void* d_out, int out_size){
  (void)in_sizes; (void)n_in; (void)out_size;
  const float* t1 = (const float*)d_in[0];
  const float* t2 = (const float*)d_in[1];
  const float* t3 = (const float*)d_in[2];
  const float* t4 = (const float*)d_in[3];
  const float* t5 = (const float*)d_in[4];
  float* out = (float*)d_out;

  void* flagp = nullptr;
  cudaGetSymbolAddress(&flagp, g_flag);
  cudaMemsetAsync(flagp, 0, sizeof(int)*NB*TOTC, 0);

  k1_gather<<<BTOK/256, 256>>>(t1,t2,t3,t4,t5,(const float*)d_in[5]);
  k35_fused<<<NB*TOTC, 256>>>(t1,t2,t3,t4,t5,
                              (const float*)d_in[8],(const float*)d_in[6],
                              (const float*)d_in[7],(const float*)d_in[9],
                              (const float*)d_in[10],(const float*)d_in[11],
                              (const float*)d_in[13],(const float*)d_in[12],
                              (const float*)d_in[23],(const float*)d_in[24],
                              (const float*)d_in[25],(const float*)d_in[26],
                              (const float*)d_in[31], out);
  k6_m1   <<<NB, 512>>>(t5,(const float*)d_in[14],(const float*)d_in[15],
                        (const float*)d_in[16],(const float*)d_in[17],
                        (const float*)d_in[18],(const float*)d_in[19],
                        (const float*)d_in[20],(const float*)d_in[21],
                        (const float*)d_in[22],(const float*)d_in[27],
                        (const float*)d_in[28],(const float*)d_in[29],
                        (const float*)d_in[30],(const float*)d_in[31], out);
}

// round 12
// speedup vs baseline: 1.4587x; 1.4587x over previous
#include <cuda_runtime.h>
#include <math.h>

// ---------------- problem geometry ----------------
#define LTOT 28928          // tokens per batch across seqs 0..3
#define BTOK 231424         // 8 * LTOT
#define TOTC 452            // chunks (T=64) per batch: 341+85+21+5
#define NB   8

// ---------------- static device scratch ----------------
__device__ __align__(16) float g_P[NB*TOTC*256];  // per-chunk product of a
__device__ __align__(16) float g_S[NB*TOTC*256];  // per-chunk local scan end
__device__ __align__(16) float g_H[NB*TOTC*256];  // h_start per chunk

__constant__ int c_plen[5]  = {16384,4096,1024,256,64};      // spatial size per tensor (= ch stride)
__constant__ int c_bs[5]    = {131072,65536,24576,8192,3072};// batch stride per tensor
__constant__ int c_obase[5] = {0,1048576,1572864,1769472,1835008};
__constant__ int c_O[4]     = {0,21824,27264,28608};         // seq offsets within a batch
__constant__ int c_CB[4]    = {0,341,426,447};               // chunk base per seq
__constant__ int c_NC[4]    = {341,85,21,5};                 // chunks per seq

__device__ __forceinline__ float siluf(float x){ return x * (1.0f/(1.0f+__expf(-x))); }
__device__ __forceinline__ float softplusf(float x){ return (x>20.0f)? x : log1pf(__expf(x)); }

// ======= shared record recompute (now includes gather + in-proj) ==========
// x8h[c][j]: raw input channel c, token tb-4+j (j=0..67)
// xi[d][j]:  in-proj xi channel d, token tb-4+j  (reused as y[16][68] later)
// zsh[d][t]: in-proj z channel d (k5 only)
struct alignas(16) RecSmem {
  float  xi[16][68];      // 4352 B (aliased as y after conv)
  float  xcs[16][68];     // 4352 B
  float  x8h[8][68];      // 2176 B
  float  zsh[16][64];     // 4096 B (k5 only)
  float2 dldu[16][65];    // 8320 B {delta, delta*xc}
  float2 BC[16][65];      // 8320 B {B, C}
  float  dtv[64];         // 256 B
  float  xp[564];         // 33 rows, stride 17 (2256 B)
  float  iw[256];         // in_w (32,8)
  float  cw[64], cb[16], dtw[16], dtb[16];
};

template<bool WANTZ>
__device__ __forceinline__ void rec_compute(RecSmem& S, int tid, int b, int s, int cis,
    const float* __restrict__ tp, int ibase, int plen,
    const float* __restrict__ t1, const float* __restrict__ t2,
    const float* __restrict__ t3, const float* __restrict__ t4,
    const float* __restrict__ t5,
    const float* __restrict__ in_w, const float* __restrict__ xproj_w,
    const float* __restrict__ conv_w, const float* __restrict__ conv_b,
    const float* __restrict__ dt_w,  const float* __restrict__ dt_b){
  // params
  for (int i=tid;i<528;i+=256){ int row=i>>4, col=i&15; S.xp[row*17+col]=xproj_w[i]; }
  S.iw[tid]=in_w[tid];
  if (tid<64) S.cw[tid]=conv_w[tid];
  if (tid<16){ S.cb[tid]=conv_b[tid]; S.dtw[tid]=dt_w[tid]; S.dtb[tid]=dt_b[tid]; }
  // raw x8 staging: main 64 tokens (coalesced float4), 4-token halo (general map)
  if (tid<128){
    int ch=tid>>4, q=tid&15;
    float4 w = *reinterpret_cast<const float4*>(&tp[ibase + ch*plen + q*4]);
    S.x8h[ch][4+q*4+0]=w.x; S.x8h[ch][4+q*4+1]=w.y;
    S.x8h[ch][4+q*4+2]=w.z; S.x8h[ch][4+q*4+3]=w.w;
  } else if (tid<160){
    int u=tid-128, j=u>>3, c=u&7;
    float v=0.f;
    if (cis>0){
      int p = cis*64 - 4 + j;       // position within seq s (>=60, same seq)
      int i2=s, pp=p;
      while (pp >= c_plen[i2]) { pp -= c_plen[i2]; ++i2; }
      const float* hp = (i2==0)?t1:(i2==1)?t2:(i2==2)?t3:(i2==3)?t4:t5;
      v = hp[b*c_bs[i2] + (8*s+c)*c_plen[i2] + pp];
    }
    S.x8h[c][j]=v;
  }
  __syncthreads();
  // in-proj xi: 16 d x 68 tokens
  for (int i=tid;i<1088;i+=256){
    int d=i/68, j=i-d*68;
    float acc=0.f;
    #pragma unroll
    for (int c=0;c<8;c++) acc += S.x8h[c][j]*S.iw[d*8+c];
    S.xi[d][j]=acc;
  }
  // in-proj z (k5 only): 16 d x 64 tokens
  if (WANTZ){
    #pragma unroll
    for (int k=0;k<4;k++){
      int i=tid+k*256;
      int dd=i>>6, t=i&63;
      float acc=0.f;
      #pragma unroll
      for (int c=0;c<8;c++) acc += S.x8h[c][t+4]*S.iw[(16+dd)*8+c];
      S.zsh[dd][t]=acc;
    }
  }
  __syncthreads();
  // conv + silu -> xcs
  #pragma unroll
  for (int k=0;k<4;k++){
    int idx = tid + k*256;
    int d = idx>>6, t = idx&63;
    float acc = S.cb[d];
    #pragma unroll
    for (int kk=0;kk<4;kk++) acc += S.cw[d*4+kk]*S.xi[d][t+1+kk];
    S.xcs[d][t] = siluf(acc);
  }
  __syncthreads();
  // dt row (xp row 0)
  if (tid<64){
    float v=0.f;
    #pragma unroll
    for (int d=0;d<16;d++) v += S.xcs[d][tid]*S.xp[d];
    S.dtv[tid]=v;
  }
  __syncthreads();
  // B and C dots, t-blocked
  {
    int j = tid & 15;
    int t0 = (tid >> 4) << 2;
    float aB0=0.f,aB1=0.f,aB2=0.f,aB3=0.f;
    float aC0=0.f,aC1=0.f,aC2=0.f,aC3=0.f;
    #pragma unroll
    for (int d=0;d<16;d++){
      float4 x4 = *reinterpret_cast<const float4*>(&S.xcs[d][t0]);
      float wb = S.xp[(1+j)*17+d];
      aB0 += x4.x*wb; aB1 += x4.y*wb; aB2 += x4.z*wb; aB3 += x4.w*wb;
      if (WANTZ){
        float wc = S.xp[(17+j)*17+d];
        aC0 += x4.x*wc; aC1 += x4.y*wc; aC2 += x4.z*wc; aC3 += x4.w*wc;
      }
    }
    S.BC[j][t0+0] = make_float2(aB0, aC0);
    S.BC[j][t0+1] = make_float2(aB1, aC1);
    S.BC[j][t0+2] = make_float2(aB2, aC2);
    S.BC[j][t0+3] = make_float2(aB3, aC3);
  }
  // delta + delta*xc
  #pragma unroll
  for (int k=0;k<4;k++){
    int idx = tid + k*256;
    int d = idx>>6, t = idx&63;
    float del = softplusf(S.dtv[t]*S.dtw[d]+S.dtb[d]);
    S.dldu[d][t] = make_float2(del, del*S.xcs[d][t]);
  }
  __syncthreads();
}

// ---------------- K3: fused gather+in-proj+record + phase A (P,S) ---------
__global__ void __launch_bounds__(256,5)
k3_scanA(const float* __restrict__ t1, const float* __restrict__ t2,
         const float* __restrict__ t3, const float* __restrict__ t4,
         const float* __restrict__ t5,
         const float* __restrict__ in_w, const float* __restrict__ xproj_w,
         const float* __restrict__ conv_w, const float* __restrict__ conv_b,
         const float* __restrict__ dt_w, const float* __restrict__ dt_b,
         const float* __restrict__ Alog){
  __shared__ RecSmem S;
  int blk = blockIdx.x;
  int b = blk / TOTC, cg = blk % TOTC;
  int s = (cg>=341)+(cg>=426)+(cg>=447);
  int cis = cg - c_CB[s];
  int tid = threadIdx.x;
  int ti = s, pp = cis*64;
  while (pp >= c_plen[ti]) { pp -= c_plen[ti]; ++ti; }
  const float* tp = (ti==0)?t1:(ti==1)?t2:(ti==2)?t3:(ti==3)?t4:t5;
  int ibase = b*c_bs[ti] + (8*s)*c_plen[ti] + pp;
  rec_compute<false>(S, tid, b, s, cis, tp, ibase, c_plen[ti],
                     t1,t2,t3,t4,t5, in_w, xproj_w, conv_w, conv_b, dt_w, dt_b);
  if (tid < 64){
    int d = tid>>2, ng = tid&3;
    float4 al = *reinterpret_cast<const float4*>(&Alog[d*16 + 4*ng]);
    const float L2E = 1.4426950408889634f;
    float ac0=-__expf(al.x)*L2E, ac1=-__expf(al.y)*L2E,
          ac2=-__expf(al.z)*L2E, ac3=-__expf(al.w)*L2E;
    float h0=0.f,h1=0.f,h2=0.f,h3=0.f;
    float P0=1.f,P1=1.f,P2=1.f,P3=1.f;
    #pragma unroll 4
    for (int t=0;t<64;t++){
      float2 du = S.dldu[d][t];
      float b0 = S.BC[4*ng+0][t].x;
      float b1 = S.BC[4*ng+1][t].x;
      float b2 = S.BC[4*ng+2][t].x;
      float b3 = S.BC[4*ng+3][t].x;
      float a0=exp2f(du.x*ac0), a1=exp2f(du.x*ac1),
            a2=exp2f(du.x*ac2), a3=exp2f(du.x*ac3);
      h0 = a0*h0 + du.y*b0;  P0 *= a0;
      h1 = a1*h1 + du.y*b1;  P1 *= a1;
      h2 = a2*h2 + du.y*b2;  P2 *= a2;
      h3 = a3*h3 + du.y*b3;  P3 *= a3;
    }
    int idx = (b*TOTC+cg)*256 + d*16 + 4*ng;
    *reinterpret_cast<float4*>(&g_P[idx]) = make_float4(P0,P1,P2,P3);
    *reinterpret_cast<float4*>(&g_S[idx]) = make_float4(h0,h1,h2,h3);
  }
}

// ---------------- K4: chunk-prefix scan, software-pipelined ----------------
__global__ void k4_chunk(){
  constexpr int U = 16;
  int b = blockIdx.x >> 2, s = blockIdx.x & 3;
  int tid = threadIdx.x;
  int base = (b*TOTC + c_CB[s])*256 + tid;
  int nc = c_NC[s];
  int nbatch = (nc + U - 1)/U;
  float PA[U],SA[U],PB[U],SB[U];
  #pragma unroll
  for (int u=0;u<U;u++){
    if (u<nc){ int idx=base+u*256; PA[u]=g_P[idx]; SA[u]=g_S[idx]; }
    else { PA[u]=1.f; SA[u]=0.f; }
  }
  float H=0.f;
  for (int bi=0; bi<nbatch; bi+=2){
    if (bi+1<nbatch){
      #pragma unroll
      for (int u=0;u<U;u++){
        int c=(bi+1)*U+u;
        if (c<nc){ int idx=base+c*256; PB[u]=g_P[idx]; SB[u]=g_S[idx]; }
        else { PB[u]=1.f; SB[u]=0.f; }
      }
    }
    #pragma unroll
    for (int u=0;u<U;u++){
      int c=bi*U+u;
      if (c<nc){ g_H[base+c*256]=H; H = PA[u]*H + SA[u]; }
    }
    if (bi+2<nbatch){
      #pragma unroll
      for (int u=0;u<U;u++){
        int c=(bi+2)*U+u;
        if (c<nc){ int idx=base+c*256; PA[u]=g_P[idx]; SA[u]=g_S[idx]; }
        else { PA[u]=1.f; SA[u]=0.f; }
      }
    }
    if (bi+1<nbatch){
      #pragma unroll
      for (int u=0;u<U;u++){
        int c=(bi+1)*U+u;
        if (c<nc){ g_H[base+c*256]=H; H = PB[u]*H + SB[u]; }
      }
    }
  }
}

// ---------------- K5: fused recompute + phase C + epilogue + scatter -------
struct alignas(16) K5Smem {
  RecSmem R;
  float ow[128], pwm[64], pbv[8], gv[8], nbvv[8], Dvv[16];
  float skip; float pad3[3];
};

__global__ void __launch_bounds__(256,5)
k5_scanC(const float* __restrict__ t1, const float* __restrict__ t2,
         const float* __restrict__ t3, const float* __restrict__ t4,
         const float* __restrict__ t5,
         const float* __restrict__ in_w, const float* __restrict__ xproj_w,
         const float* __restrict__ conv_w, const float* __restrict__ conv_b,
         const float* __restrict__ dt_w, const float* __restrict__ dt_b,
         const float* __restrict__ Alog,
         const float* __restrict__ out_w, const float* __restrict__ Dv,
         const float* __restrict__ ng_, const float* __restrict__ nbv,
         const float* __restrict__ pw, const float* __restrict__ pb,
         const float* __restrict__ skipp, float* __restrict__ out){
  __shared__ K5Smem S;
  int blk = blockIdx.x;
  int b = blk / TOTC, cg = blk % TOTC;
  int s = (cg>=341)+(cg>=426)+(cg>=447);
  int cis = cg - c_CB[s];
  int tid = threadIdx.x;
  int ti = s, pp = cis*64;
  while (pp >= c_plen[ti]) { pp -= c_plen[ti]; ++ti; }
  const float* tp = (ti==0)?t1:(ti==1)?t2:(ti==2)?t3:(ti==3)?t4:t5;
  int ibase = b*c_bs[ti] + (8*s)*c_plen[ti] + pp;
  // epilogue params (disjoint smem; ordered by rec_compute barriers)
  if (tid<128) S.ow[tid]=out_w[tid];
  else {
    int u = tid-128;
    if (u<64) S.pwm[u]=pw[u];
    else if (u<72) S.pbv[u-64]=pb[u-64];
    else if (u<80) S.gv[u-72]=ng_[u-72];
    else if (u<88) S.nbvv[u-80]=nbv[u-80];
    else if (u<104) S.Dvv[u-88]=Dv[u-88];
    else if (u==104) S.skip = skipp[0];
  }
  rec_compute<true>(S.R, tid, b, s, cis, tp, ibase, c_plen[ti],
                    t1,t2,t3,t4,t5, in_w, xproj_w, conv_w, conv_b, dt_w, dt_b);
  float (*ysh)[68] = reinterpret_cast<float (*)[68]>(S.R.xi);  // xi dead after conv
  if (tid < 64){
    int d = tid>>2, ngi = tid&3;
    float4 al = *reinterpret_cast<const float4*>(&Alog[d*16 + 4*ngi]);
    const float L2E = 1.4426950408889634f;
    float ac0=-__expf(al.x)*L2E, ac1=-__expf(al.y)*L2E,
          ac2=-__expf(al.z)*L2E, ac3=-__expf(al.w)*L2E;
    int hidx = (b*TOTC+cg)*256 + d*16 + 4*ngi;
    float4 h4 = *reinterpret_cast<const float4*>(&g_H[hidx]);
    float h0=h4.x,h1=h4.y,h2=h4.z,h3=h4.w;
    #pragma unroll 4
    for (int t=0;t<64;t++){
      float2 du = S.R.dldu[d][t];
      float2 bc0 = S.R.BC[4*ngi+0][t];
      float2 bc1 = S.R.BC[4*ngi+1][t];
      float2 bc2 = S.R.BC[4*ngi+2][t];
      float2 bc3 = S.R.BC[4*ngi+3][t];
      float a0=exp2f(du.x*ac0), a1=exp2f(du.x*ac1),
            a2=exp2f(du.x*ac2), a3=exp2f(du.x*ac3);
      h0 = a0*h0 + du.y*bc0.x;
      h1 = a1*h1 + du.y*bc1.x;
      h2 = a2*h2 + du.y*bc2.x;
      h3 = a3*h3 + du.y*bc3.x;
      float pr = h0*bc0.y + h1*bc1.y + h2*bc2.y + h3*bc3.y;
      pr += __shfl_xor_sync(0xffffffffu, pr, 1);
      pr += __shfl_xor_sync(0xffffffffu, pr, 2);
      if (ngi==0) ysh[d][t]=pr;
    }
  }
  __syncthreads();
  if (tid < 64){
    int t = tid;
    float yf[16];
    #pragma unroll
    for (int dd=0;dd<16;dd++){
      float z = S.R.zsh[dd][t];
      yf[dd] = (ysh[dd][t] + S.R.xcs[dd][t]*S.Dvv[dd]) * siluf(z);
    }
    float o[8]; float mu=0.f;
    #pragma unroll
    for (int ch=0;ch<8;ch++){
      float acc = S.skip * S.R.x8h[ch][t+4];
      #pragma unroll
      for (int dd=0;dd<16;dd++) acc += yf[dd]*S.ow[ch*16+dd];
      o[ch]=acc; mu+=acc;
    }
    mu *= 0.125f;
    float var=0.f;
    #pragma unroll
    for (int ch=0;ch<8;ch++){ float dv=o[ch]-mu; var += dv*dv; }
    var *= 0.125f;
    float rs = rsqrtf(var + 1e-5f);
    float ln[8];
    #pragma unroll
    for (int ch=0;ch<8;ch++) ln[ch] = (o[ch]-mu)*rs*S.gv[ch] + S.nbvv[ch];
    int base = c_obase[ti] + ibase + t;
    #pragma unroll
    for (int j=0;j<8;j++){
      float acc = S.pbv[j];
      #pragma unroll
      for (int ch=0;ch<8;ch++) acc += ln[ch]*S.pwm[j*8+ch];
      out[base + j*c_plen[ti]] = acc;
    }
  }
}

// ---------------- K6: whole m1 path (c5, L=64, dm=16) in one kernel ----------------
__global__ void k6_m1(const float* __restrict__ t5, const float* __restrict__ in_w,
                      const float* __restrict__ conv_w, const float* __restrict__ conv_b,
                      const float* __restrict__ xproj_w, const float* __restrict__ dt_w,
                      const float* __restrict__ dt_b, const float* __restrict__ Alog,
                      const float* __restrict__ Dv, const float* __restrict__ out_w,
                      const float* __restrict__ ng, const float* __restrict__ nbv,
                      const float* __restrict__ pw, const float* __restrict__ pb,
                      const float* __restrict__ skipp, float* __restrict__ out){
  __shared__ float s_x[64][16];
  __shared__ float s_xi[64][32];
  __shared__ float s_z[64][32];
  __shared__ float s_xc[64][32];
  __shared__ float s_B[64][16];
  __shared__ float s_C[64][16];
  __shared__ float s_dt[64];
  __shared__ float s_y[64][32];
  int b = blockIdx.x, tid = threadIdx.x;
  for (int i=tid;i<64*16;i+=512){
    int t=i>>4, c=i&15;
    s_x[t][c] = t5[b*3072 + (32+c)*64 + t];
  }
  __syncthreads();
  for (int i=tid;i<64*64;i+=512){
    int t=i>>6, j=i&63;
    float v=0.f;
    #pragma unroll
    for (int c=0;c<16;c++) v += s_x[t][c]*in_w[j*16+c];
    if (j<32) s_xi[t][j]=v; else s_z[t][j-32]=v;
  }
  __syncthreads();
  for (int i=tid;i<64*32;i+=512){
    int t=i>>5, d=i&31;
    float acc = conv_b[d];
    #pragma unroll
    for (int k=0;k<4;k++){
      int tt = t-3+k;
      if (tt>=0) acc += conv_w[d*4+k]*s_xi[tt][d];
    }
    s_xc[t][d] = siluf(acc);
  }
  __syncthreads();
  for (int i=tid;i<64*33;i+=512){
    int t=i/33, j=i%33;
    float v=0.f;
    #pragma unroll
    for (int d=0;d<32;d++) v += s_xc[t][d]*xproj_w[j*32+d];
    if (j==0) s_dt[t]=v;
    else if (j<17) s_B[t][j-1]=v;
    else s_C[t][j-17]=v;
  }
  __syncthreads();
  for (int i=tid;i<64*32;i+=512){
    int t=i>>5, d=i&31;
    s_xi[t][d] = softplusf(s_dt[t]*dt_w[d] + dt_b[d]);
  }
  __syncthreads();
  {
    int d=tid>>4, n=tid&15;
    float ac = -__expf(Alog[d*16+n])*1.4426950408889634f;
    float h=0.f;
    for (int t=0;t<64;t++){
      float dl = s_xi[t][d];
      float a = exp2f(dl*ac);
      h = a*h + dl*s_xc[t][d]*s_B[t][n];
      float pr = h*s_C[t][n];
      pr += __shfl_xor_sync(0xffffffffu, pr, 8);
      pr += __shfl_xor_sync(0xffffffffu, pr, 4);
      pr += __shfl_xor_sync(0xffffffffu, pr, 2);
      pr += __shfl_xor_sync(0xffffffffu, pr, 1);
      if (n==0) s_y[t][d]=pr;
    }
  }
  __syncthreads();
  if (tid<64){
    int t=tid;
    float skip = skipp[0];
    float yf[32];
    #pragma unroll
    for (int d=0;d<32;d++) yf[d] = (s_y[t][d] + s_xc[t][d]*Dv[d]) * siluf(s_z[t][d]);
    float o[16]; float mu=0.f;
    #pragma unroll
    for (int ch=0;ch<16;ch++){
      float acc = skip * s_x[t][ch];
      #pragma unroll
      for (int d=0;d<32;d++) acc += yf[d]*out_w[ch*32+d];
      o[ch]=acc; mu+=acc;
    }
    mu *= (1.0f/16.0f);
    float var=0.f;
    #pragma unroll
    for (int ch=0;ch<16;ch++){ float dv=o[ch]-mu; var+=dv*dv; }
    var *= (1.0f/16.0f);
    float rs = rsqrtf(var+1e-5f);
    float ln[16];
    #pragma unroll
    for (int ch=0;ch<16;ch++) ln[ch] = (o[ch]-mu)*rs*ng[ch]+nbv[ch];
    #pragma unroll
    for (int j=0;j<16;j++){
      float acc = pb[j];
      #pragma unroll
      for (int ch=0;ch<16;ch++) acc += ln[ch]*pw[j*16+ch];
      out[1835008 + b*3072 + (32+j)*64 + t] = acc;
    }
  }
}

// ---------------- launch ----------------
extern "C" void kernel_launch(void* const* d_in, const int* in_sizes, int n_in,
                              void* d_out, int out_size){
  (void)in_sizes; (void)n_in; (void)out_size;
  const float* t1 = (const float*)d_in[0];
  const float* t2 = (const float*)d_in[1];
  const float* t3 = (const float*)d_in[2];
  const float* t4 = (const float*)d_in[3];
  const float* t5 = (const float*)d_in[4];
  float* out = (float*)d_out;

  k3_scanA<<<NB*TOTC, 256>>>(t1,t2,t3,t4,t5,
                             (const float*)d_in[5],(const float*)d_in[8],
                             (const float*)d_in[6],(const float*)d_in[7],
                             (const float*)d_in[9],(const float*)d_in[10],
                             (const float*)d_in[11]);
  k4_chunk<<<32, 256>>>();
  k5_scanC<<<NB*TOTC, 256>>>(t1,t2,t3,t4,t5,
                             (const float*)d_in[5],(const float*)d_in[8],
                             (const float*)d_in[6],(const float*)d_in[7],
                             (const float*)d_in[9],(const float*)d_in[10],
                             (const float*)d_in[11],
                             (const float*)d_in[13],(const float*)d_in[12],
                             (const float*)d_in[23],(const float*)d_in[24],
                             (const float*)d_in[25],(const float*)d_in[26],
                             (const float*)d_in[31], out);
  k6_m1   <<<NB, 512>>>(t5,(const float*)d_in[14],(const float*)d_in[15],
                        (const float*)d_in[16],(const float*)d_in[17],
                        (const float*)d_in[18],(const float*)d_in[19],
                        (const float*)d_in[20],(const float*)d_in[21],
                        (const float*)d_in[22],(const float*)d_in[27],
                        (const float*)d_in[28],(const float*)d_in[29],
                        (const float*)d_in[30],(const float*)d_in[31], out);
}

// round 13
// speedup vs baseline: 1.4912x; 1.0223x over previous
#include <cuda_runtime.h>
#include <math.h>

// ---------------- problem geometry ----------------
#define LTOT 28928          // tokens per batch across seqs 0..3
#define BTOK 231424         // 8 * LTOT
#define TOTC 452            // chunks (T=64) per batch: 341+85+21+5
#define NB   8

// ---------------- static device scratch ----------------
__device__ __align__(16) float g_P[NB*TOTC*256];  // per-chunk product of a
__device__ __align__(16) float g_S[NB*TOTC*256];  // per-chunk local scan end
__device__ __align__(16) float g_H[NB*TOTC*256];  // h_start per chunk

__constant__ int c_plen[5]  = {16384,4096,1024,256,64};      // spatial size per tensor (= ch stride)
__constant__ int c_bs[5]    = {131072,65536,24576,8192,3072};// batch stride per tensor
__constant__ int c_obase[5] = {0,1048576,1572864,1769472,1835008};
__constant__ int c_O[4]     = {0,21824,27264,28608};         // seq offsets within a batch
__constant__ int c_CB[4]    = {0,341,426,447};               // chunk base per seq
__constant__ int c_NC[4]    = {341,85,21,5};                 // chunks per seq

__device__ __forceinline__ float siluf(float x){ return x * (1.0f/(1.0f+__expf(-x))); }
__device__ __forceinline__ float softplusf(float x){ return (x>20.0f)? x : log1pf(__expf(x)); }

// ======= shared record recompute (includes gather + in-proj) ==========
struct alignas(16) RecSmem {
  float  xi[16][68];      // 4352 B (aliased as y after conv)
  float  xcs[16][68];     // 4352 B
  float  x8h[8][68];      // 2176 B
  float  zsh[16][64];     // 4096 B (k5 only)
  float2 dldu[16][65];    // 8320 B {delta, delta*xc}
  float2 BC[16][65];      // 8320 B {B, C}
  float  dtv[64];         // 256 B
  float  xp[564];         // 33 rows, stride 17 (2256 B)
  float  iw[256];         // in_w (32,8)
  float  cw[64], cb[16], dtw[16], dtb[16];
};

template<bool WANTZ>
__device__ __forceinline__ void rec_compute(RecSmem& S, int tid, int b, int s, int cis,
    const float* __restrict__ tp, int ibase, int plen,
    const float* __restrict__ t1, const float* __restrict__ t2,
    const float* __restrict__ t3, const float* __restrict__ t4,
    const float* __restrict__ t5,
    const float* __restrict__ in_w, const float* __restrict__ xproj_w,
    const float* __restrict__ conv_w, const float* __restrict__ conv_b,
    const float* __restrict__ dt_w,  const float* __restrict__ dt_b){
  for (int i=tid;i<528;i+=256){ int row=i>>4, col=i&15; S.xp[row*17+col]=xproj_w[i]; }
  S.iw[tid]=in_w[tid];
  if (tid<64) S.cw[tid]=conv_w[tid];
  if (tid<16){ S.cb[tid]=conv_b[tid]; S.dtw[tid]=dt_w[tid]; S.dtb[tid]=dt_b[tid]; }
  if (tid<128){
    int ch=tid>>4, q=tid&15;
    float4 w = *reinterpret_cast<const float4*>(&tp[ibase + ch*plen + q*4]);
    S.x8h[ch][4+q*4+0]=w.x; S.x8h[ch][4+q*4+1]=w.y;
    S.x8h[ch][4+q*4+2]=w.z; S.x8h[ch][4+q*4+3]=w.w;
  } else if (tid<160){
    int u=tid-128, j=u>>3, c=u&7;
    float v=0.f;
    if (cis>0){
      int p = cis*64 - 4 + j;
      int i2=s, pp=p;
      while (pp >= c_plen[i2]) { pp -= c_plen[i2]; ++i2; }
      const float* hp = (i2==0)?t1:(i2==1)?t2:(i2==2)?t3:(i2==3)?t4:t5;
      v = hp[b*c_bs[i2] + (8*s+c)*c_plen[i2] + pp];
    }
    S.x8h[c][j]=v;
  }
  __syncthreads();
  for (int i=tid;i<1088;i+=256){
    int d=i/68, j=i-d*68;
    float acc=0.f;
    #pragma unroll
    for (int c=0;c<8;c++) acc += S.x8h[c][j]*S.iw[d*8+c];
    S.xi[d][j]=acc;
  }
  if (WANTZ){
    #pragma unroll
    for (int k=0;k<4;k++){
      int i=tid+k*256;
      int dd=i>>6, t=i&63;
      float acc=0.f;
      #pragma unroll
      for (int c=0;c<8;c++) acc += S.x8h[c][t+4]*S.iw[(16+dd)*8+c];
      S.zsh[dd][t]=acc;
    }
  }
  __syncthreads();
  #pragma unroll
  for (int k=0;k<4;k++){
    int idx = tid + k*256;
    int d = idx>>6, t = idx&63;
    float acc = S.cb[d];
    #pragma unroll
    for (int kk=0;kk<4;kk++) acc += S.cw[d*4+kk]*S.xi[d][t+1+kk];
    S.xcs[d][t] = siluf(acc);
  }
  __syncthreads();
  if (tid<64){
    float v=0.f;
    #pragma unroll
    for (int d=0;d<16;d++) v += S.xcs[d][tid]*S.xp[d];
    S.dtv[tid]=v;
  }
  __syncthreads();
  {
    int j = tid & 15;
    int t0 = (tid >> 4) << 2;
    float aB0=0.f,aB1=0.f,aB2=0.f,aB3=0.f;
    float aC0=0.f,aC1=0.f,aC2=0.f,aC3=0.f;
    #pragma unroll
    for (int d=0;d<16;d++){
      float4 x4 = *reinterpret_cast<const float4*>(&S.xcs[d][t0]);
      float wb = S.xp[(1+j)*17+d];
      aB0 += x4.x*wb; aB1 += x4.y*wb; aB2 += x4.z*wb; aB3 += x4.w*wb;
      if (WANTZ){
        float wc = S.xp[(17+j)*17+d];
        aC0 += x4.x*wc; aC1 += x4.y*wc; aC2 += x4.z*wc; aC3 += x4.w*wc;
      }
    }
    S.BC[j][t0+0] = make_float2(aB0, aC0);
    S.BC[j][t0+1] = make_float2(aB1, aC1);
    S.BC[j][t0+2] = make_float2(aB2, aC2);
    S.BC[j][t0+3] = make_float2(aB3, aC3);
  }
  #pragma unroll
  for (int k=0;k<4;k++){
    int idx = tid + k*256;
    int d = idx>>6, t = idx&63;
    float del = softplusf(S.dtv[t]*S.dtw[d]+S.dtb[d]);
    S.dldu[d][t] = make_float2(del, del*S.xcs[d][t]);
  }
  __syncthreads();
}

// ---------------- K3: fused gather+in-proj+record + phase A (P,S) ---------
__global__ void __launch_bounds__(256,5)
k3_scanA(const float* __restrict__ t1, const float* __restrict__ t2,
         const float* __restrict__ t3, const float* __restrict__ t4,
         const float* __restrict__ t5,
         const float* __restrict__ in_w, const float* __restrict__ xproj_w,
         const float* __restrict__ conv_w, const float* __restrict__ conv_b,
         const float* __restrict__ dt_w, const float* __restrict__ dt_b,
         const float* __restrict__ Alog){
  __shared__ RecSmem S;
  int blk = blockIdx.x;
  int b = blk / TOTC, cg = blk % TOTC;
  int s = (cg>=341)+(cg>=426)+(cg>=447);
  int cis = cg - c_CB[s];
  int tid = threadIdx.x;
  int ti = s, pp = cis*64;
  while (pp >= c_plen[ti]) { pp -= c_plen[ti]; ++ti; }
  const float* tp = (ti==0)?t1:(ti==1)?t2:(ti==2)?t3:(ti==3)?t4:t5;
  int ibase = b*c_bs[ti] + (8*s)*c_plen[ti] + pp;
  rec_compute<false>(S, tid, b, s, cis, tp, ibase, c_plen[ti],
                     t1,t2,t3,t4,t5, in_w, xproj_w, conv_w, conv_b, dt_w, dt_b);
  if (tid < 64){
    int d = tid>>2, ng = tid&3;
    float4 al = *reinterpret_cast<const float4*>(&Alog[d*16 + 4*ng]);
    const float L2E = 1.4426950408889634f;
    float ac0=-__expf(al.x)*L2E, ac1=-__expf(al.y)*L2E,
          ac2=-__expf(al.z)*L2E, ac3=-__expf(al.w)*L2E;
    float h0=0.f,h1=0.f,h2=0.f,h3=0.f;
    float P0=1.f,P1=1.f,P2=1.f,P3=1.f;
    #pragma unroll 4
    for (int t=0;t<64;t++){
      float2 du = S.dldu[d][t];
      float b0 = S.BC[4*ng+0][t].x;
      float b1 = S.BC[4*ng+1][t].x;
      float b2 = S.BC[4*ng+2][t].x;
      float b3 = S.BC[4*ng+3][t].x;
      float a0=exp2f(du.x*ac0), a1=exp2f(du.x*ac1),
            a2=exp2f(du.x*ac2), a3=exp2f(du.x*ac3);
      h0 = a0*h0 + du.y*b0;  P0 *= a0;
      h1 = a1*h1 + du.y*b1;  P1 *= a1;
      h2 = a2*h2 + du.y*b2;  P2 *= a2;
      h3 = a3*h3 + du.y*b3;  P3 *= a3;
    }
    int idx = (b*TOTC+cg)*256 + d*16 + 4*ng;
    *reinterpret_cast<float4*>(&g_P[idx]) = make_float4(P0,P1,P2,P3);
    *reinterpret_cast<float4*>(&g_S[idx]) = make_float4(h0,h1,h2,h3);
  }
}

// ---------------- K4: chunk-prefix scan, software-pipelined ----------------
__global__ void k4_chunk(){
  constexpr int U = 16;
  int b = blockIdx.x >> 2, s = blockIdx.x & 3;
  int tid = threadIdx.x;
  int base = (b*TOTC + c_CB[s])*256 + tid;
  int nc = c_NC[s];
  int nbatch = (nc + U - 1)/U;
  float PA[U],SA[U],PB[U],SB[U];
  #pragma unroll
  for (int u=0;u<U;u++){
    if (u<nc){ int idx=base+u*256; PA[u]=g_P[idx]; SA[u]=g_S[idx]; }
    else { PA[u]=1.f; SA[u]=0.f; }
  }
  float H=0.f;
  for (int bi=0; bi<nbatch; bi+=2){
    if (bi+1<nbatch){
      #pragma unroll
      for (int u=0;u<U;u++){
        int c=(bi+1)*U+u;
        if (c<nc){ int idx=base+c*256; PB[u]=g_P[idx]; SB[u]=g_S[idx]; }
        else { PB[u]=1.f; SB[u]=0.f; }
      }
    }
    #pragma unroll
    for (int u=0;u<U;u++){
      int c=bi*U+u;
      if (c<nc){ g_H[base+c*256]=H; H = PA[u]*H + SA[u]; }
    }
    if (bi+2<nbatch){
      #pragma unroll
      for (int u=0;u<U;u++){
        int c=(bi+2)*U+u;
        if (c<nc){ int idx=base+c*256; PA[u]=g_P[idx]; SA[u]=g_S[idx]; }
        else { PA[u]=1.f; SA[u]=0.f; }
      }
    }
    if (bi+1<nbatch){
      #pragma unroll
      for (int u=0;u<U;u++){
        int c=(bi+1)*U+u;
        if (c<nc){ g_H[base+c*256]=H; H = PB[u]*H + SB[u]; }
      }
    }
  }
}

// ---------------- K5: fused recompute + phase C + epilogue + scatter -------
struct alignas(16) K5Smem {
  RecSmem R;
  float ow[128], pwm[64], pbv[8], gv[8], nbvv[8], Dvv[16];
  float skip; float pad3[3];
};

__global__ void __launch_bounds__(256,5)
k5_scanC(const float* __restrict__ t1, const float* __restrict__ t2,
         const float* __restrict__ t3, const float* __restrict__ t4,
         const float* __restrict__ t5,
         const float* __restrict__ in_w, const float* __restrict__ xproj_w,
         const float* __restrict__ conv_w, const float* __restrict__ conv_b,
         const float* __restrict__ dt_w, const float* __restrict__ dt_b,
         const float* __restrict__ Alog,
         const float* __restrict__ out_w, const float* __restrict__ Dv,
         const float* __restrict__ ng_, const float* __restrict__ nbv,
         const float* __restrict__ pw, const float* __restrict__ pb,
         const float* __restrict__ skipp, float* __restrict__ out){
  __shared__ K5Smem S;
  int blk = blockIdx.x;
  int b = blk / TOTC, cg = blk % TOTC;
  int s = (cg>=341)+(cg>=426)+(cg>=447);
  int cis = cg - c_CB[s];
  int tid = threadIdx.x;
  int ti = s, pp = cis*64;
  while (pp >= c_plen[ti]) { pp -= c_plen[ti]; ++ti; }
  const float* tp = (ti==0)?t1:(ti==1)?t2:(ti==2)?t3:(ti==3)?t4:t5;
  int ibase = b*c_bs[ti] + (8*s)*c_plen[ti] + pp;
  if (tid<128) S.ow[tid]=out_w[tid];
  else {
    int u = tid-128;
    if (u<64) S.pwm[u]=pw[u];
    else if (u<72) S.pbv[u-64]=pb[u-64];
    else if (u<80) S.gv[u-72]=ng_[u-72];
    else if (u<88) S.nbvv[u-80]=nbv[u-80];
    else if (u<104) S.Dvv[u-88]=Dv[u-88];
    else if (u==104) S.skip = skipp[0];
  }
  rec_compute<true>(S.R, tid, b, s, cis, tp, ibase, c_plen[ti],
                    t1,t2,t3,t4,t5, in_w, xproj_w, conv_w, conv_b, dt_w, dt_b);
  float (*ysh)[68] = reinterpret_cast<float (*)[68]>(S.R.xi);  // xi dead after conv
  if (tid < 64){
    int d = tid>>2, ngi = tid&3;
    float4 al = *reinterpret_cast<const float4*>(&Alog[d*16 + 4*ngi]);
    const float L2E = 1.4426950408889634f;
    float ac0=-__expf(al.x)*L2E, ac1=-__expf(al.y)*L2E,
          ac2=-__expf(al.z)*L2E, ac3=-__expf(al.w)*L2E;
    int hidx = (b*TOTC+cg)*256 + d*16 + 4*ngi;
    float4 h4 = *reinterpret_cast<const float4*>(&g_H[hidx]);
    float h0=h4.x,h1=h4.y,h2=h4.z,h3=h4.w;
    #pragma unroll 4
    for (int t=0;t<64;t++){
      float2 du = S.R.dldu[d][t];
      float2 bc0 = S.R.BC[4*ngi+0][t];
      float2 bc1 = S.R.BC[4*ngi+1][t];
      float2 bc2 = S.R.BC[4*ngi+2][t];
      float2 bc3 = S.R.BC[4*ngi+3][t];
      float a0=exp2f(du.x*ac0), a1=exp2f(du.x*ac1),
            a2=exp2f(du.x*ac2), a3=exp2f(du.x*ac3);
      h0 = a0*h0 + du.y*bc0.x;
      h1 = a1*h1 + du.y*bc1.x;
      h2 = a2*h2 + du.y*bc2.x;
      h3 = a3*h3 + du.y*bc3.x;
      float pr = h0*bc0.y + h1*bc1.y + h2*bc2.y + h3*bc3.y;
      pr += __shfl_xor_sync(0xffffffffu, pr, 1);
      pr += __shfl_xor_sync(0xffffffffu, pr, 2);
      if (ngi==0) ysh[d][t]=pr;
    }
  }
  __syncthreads();
  if (tid < 64){
    int t = tid;
    float yf[16];
    #pragma unroll
    for (int dd=0;dd<16;dd++){
      float z = S.R.zsh[dd][t];
      yf[dd] = (ysh[dd][t] + S.R.xcs[dd][t]*S.Dvv[dd]) * siluf(z);
    }
    float o[8]; float mu=0.f;
    #pragma unroll
    for (int ch=0;ch<8;ch++){
      float acc = S.skip * S.R.x8h[ch][t+4];
      #pragma unroll
      for (int dd=0;dd<16;dd++) acc += yf[dd]*S.ow[ch*16+dd];
      o[ch]=acc; mu+=acc;
    }
    mu *= 0.125f;
    float var=0.f;
    #pragma unroll
    for (int ch=0;ch<8;ch++){ float dv=o[ch]-mu; var += dv*dv; }
    var *= 0.125f;
    float rs = rsqrtf(var + 1e-5f);
    float ln[8];
    #pragma unroll
    for (int ch=0;ch<8;ch++) ln[ch] = (o[ch]-mu)*rs*S.gv[ch] + S.nbvv[ch];
    int base = c_obase[ti] + ibase + t;
    #pragma unroll
    for (int j=0;j<8;j++){
      float acc = S.pbv[j];
      #pragma unroll
      for (int ch=0;ch<8;ch++) acc += ln[ch]*S.pwm[j*8+ch];
      out[base + j*c_plen[ti]] = acc;
    }
  }
}

// ---------------- K6: whole m1 path, register-blocked scan -----------------
__global__ void __launch_bounds__(512)
k6_m1(const float* __restrict__ t5, const float* __restrict__ in_w,
      const float* __restrict__ conv_w, const float* __restrict__ conv_b,
      const float* __restrict__ xproj_w, const float* __restrict__ dt_w,
      const float* __restrict__ dt_b, const float* __restrict__ Alog,
      const float* __restrict__ Dv, const float* __restrict__ out_w,
      const float* __restrict__ ng, const float* __restrict__ nbv,
      const float* __restrict__ pw, const float* __restrict__ pb,
      const float* __restrict__ skipp, float* __restrict__ out){
  __shared__ float s_iw[1024];              // in_w (64,16)
  __shared__ float s_x[64][17];
  __shared__ float s_xi[64][33];            // xi, then delta
  __shared__ float s_xc[64][33];
  __shared__ __align__(16) float s_B[64][20];
  __shared__ __align__(16) float s_C[64][20];
  __shared__ float s_dt[64];
  __shared__ float s_y[64][33];
  int b = blockIdx.x, tid = threadIdx.x;
  for (int i=tid;i<1024;i+=512) s_iw[i]=in_w[i];
  for (int i=tid;i<1024;i+=512){
    int t=i>>4, c=i&15;
    s_x[t][c] = t5[b*3072 + (32+c)*64 + t];
  }
  __syncthreads();
  for (int i=tid;i<2048;i+=512){     // in-proj xi (rows 0..31 of in_w)
    int t=i>>5, j=i&31;
    float v=0.f;
    #pragma unroll
    for (int c=0;c<16;c++) v += s_x[t][c]*s_iw[j*16+c];
    s_xi[t][j]=v;
  }
  __syncthreads();
  for (int i=tid;i<2048;i+=512){     // conv + silu
    int t=i>>5, d=i&31;
    float acc = conv_b[d];
    #pragma unroll
    for (int k=0;k<4;k++){
      int tt = t-3+k;
      if (tt>=0) acc += conv_w[d*4+k]*s_xi[tt][d];
    }
    s_xc[t][d] = siluf(acc);
  }
  __syncthreads();
  for (int i=tid;i<64*33;i+=512){    // x-proj
    int t=i/33, j=i%33;
    float v=0.f;
    #pragma unroll
    for (int d=0;d<32;d++) v += s_xc[t][d]*xproj_w[j*32+d];
    if (j==0) s_dt[t]=v;
    else if (j<17) s_B[t][j-1]=v;
    else s_C[t][j-17]=v;
  }
  __syncthreads();
  for (int i=tid;i<2048;i+=512){     // delta (overwrites s_xi)
    int t=i>>5, d=i&31;
    s_xi[t][d] = softplusf(s_dt[t]*dt_w[d] + dt_b[d]);
  }
  __syncthreads();
  if (tid < 128){                    // scan: thread=(d,ng), h[4] in regs
    int d=tid>>2, ngi=tid&3;
    float4 al = *reinterpret_cast<const float4*>(&Alog[d*16 + 4*ngi]);
    const float L2E = 1.4426950408889634f;
    float ac0=-__expf(al.x)*L2E, ac1=-__expf(al.y)*L2E,
          ac2=-__expf(al.z)*L2E, ac3=-__expf(al.w)*L2E;
    float h0=0.f,h1=0.f,h2=0.f,h3=0.f;
    #pragma unroll 4
    for (int t=0;t<64;t++){
      float dl = s_xi[t][d];
      float du = dl*s_xc[t][d];
      float4 Bv = *reinterpret_cast<const float4*>(&s_B[t][4*ngi]);
      float4 Cv = *reinterpret_cast<const float4*>(&s_C[t][4*ngi]);
      float a0=exp2f(dl*ac0), a1=exp2f(dl*ac1),
            a2=exp2f(dl*ac2), a3=exp2f(dl*ac3);
      h0 = a0*h0 + du*Bv.x;
      h1 = a1*h1 + du*Bv.y;
      h2 = a2*h2 + du*Bv.z;
      h3 = a3*h3 + du*Bv.w;
      float pr = h0*Cv.x + h1*Cv.y + h2*Cv.z + h3*Cv.w;
      pr += __shfl_xor_sync(0xffffffffu, pr, 1);
      pr += __shfl_xor_sync(0xffffffffu, pr, 2);
      if (ngi==0) s_y[t][d]=pr;
    }
  }
  __syncthreads();
  if (tid<64){
    int t=tid;
    float skip = skipp[0];
    float yf[32];
    #pragma unroll
    for (int d=0;d<32;d++){
      float z=0.f;                   // recompute z from staged x + in_w
      #pragma unroll
      for (int c=0;c<16;c++) z += s_x[t][c]*s_iw[(32+d)*16+c];
      yf[d] = (s_y[t][d] + s_xc[t][d]*Dv[d]) * siluf(z);
    }
    float o[16]; float mu=0.f;
    #pragma unroll
    for (int ch=0;ch<16;ch++){
      float acc = skip * s_x[t][ch];
      #pragma unroll
      for (int d=0;d<32;d++) acc += yf[d]*out_w[ch*32+d];
      o[ch]=acc; mu+=acc;
    }
    mu *= (1.0f/16.0f);
    float var=0.f;
    #pragma unroll
    for (int ch=0;ch<16;ch++){ float dv=o[ch]-mu; var+=dv*dv; }
    var *= (1.0f/16.0f);
    float rs = rsqrtf(var+1e-5f);
    float ln[16];
    #pragma unroll
    for (int ch=0;ch<16;ch++) ln[ch] = (o[ch]-mu)*rs*ng[ch]+nbv[ch];
    #pragma unroll
    for (int j=0;j<16;j++){
      float acc = pb[j];
      #pragma unroll
      for (int ch=0;ch<16;ch++) acc += ln[ch]*pw[j*16+ch];
      out[1835008 + b*3072 + (32+j)*64 + t] = acc;
    }
  }
}

// ---------------- launch ----------------
extern "C" void kernel_launch(void* const* d_in, const int* in_sizes, int n_in,
                              void* d_out, int out_size){
  (void)in_sizes; (void)n_in; (void)out_size;
  const float* t1 = (const float*)d_in[0];
  const float* t2 = (const float*)d_in[1];
  const float* t3 = (const float*)d_in[2];
  const float* t4 = (const float*)d_in[3];
  const float* t5 = (const float*)d_in[4];
  float* out = (float*)d_out;

  k3_scanA<<<NB*TOTC, 256>>>(t1,t2,t3,t4,t5,
                             (const float*)d_in[5],(const float*)d_in[8],
                             (const float*)d_in[6],(const float*)d_in[7],
                             (const float*)d_in[9],(const float*)d_in[10],
                             (const float*)d_in[11]);
  k4_chunk<<<32, 256>>>();
  k5_scanC<<<NB*TOTC, 256>>>(t1,t2,t3,t4,t5,
                             (const float*)d_in[5],(const float*)d_in[8],
                             (const float*)d_in[6],(const float*)d_in[7],
                             (const float*)d_in[9],(const float*)d_in[10],
                             (const float*)d_in[11],
                             (const float*)d_in[13],(const float*)d_in[12],
                             (const float*)d_in[23],(const float*)d_in[24],
                             (const float*)d_in[25],(const float*)d_in[26],
                             (const float*)d_in[31], out);
  k6_m1   <<<NB, 512>>>(t5,(const float*)d_in[14],(const float*)d_in[15],
                        (const float*)d_in[16],(const float*)d_in[17],
                        (const float*)d_in[18],(const float*)d_in[19],
                        (const float*)d_in[20],(const float*)d_in[21],
                        (const float*)d_in[22],(const float*)d_in[27],
                        (const float*)d_in[28],(const float*)d_in[29],
                        (const float*)d_in[30],(const float*)d_in[31], out);
}

// round 14
// speedup vs baseline: 1.5083x; 1.0115x over previous
#include <cuda_runtime.h>
#include <math.h>

// ---------------- problem geometry ----------------
#define LTOT 28928          // tokens per batch across seqs 0..3
#define BTOK 231424         // 8 * LTOT
#define TOTC 452            // chunks (T=64) per batch: 341+85+21+5
#define NB   8

// ---------------- static device scratch ----------------
__device__ __align__(16) float g_P[NB*TOTC*256];  // per-chunk product of a
__device__ __align__(16) float g_S[NB*TOTC*256];  // per-chunk local scan end
__device__ __align__(16) float g_H[NB*TOTC*256];  // h_start per chunk

__constant__ int c_plen[5]  = {16384,4096,1024,256,64};      // spatial size per tensor (= ch stride)
__constant__ int c_bs[5]    = {131072,65536,24576,8192,3072};// batch stride per tensor
__constant__ int c_obase[5] = {0,1048576,1572864,1769472,1835008};
__constant__ int c_O[4]     = {0,21824,27264,28608};         // seq offsets within a batch
__constant__ int c_CB[4]    = {0,341,426,447};               // chunk base per seq
__constant__ int c_NC[4]    = {341,85,21,5};                 // chunks per seq

__device__ __forceinline__ float siluf(float x){ return x * (1.0f/(1.0f+__expf(-x))); }
__device__ __forceinline__ float softplusf(float x){ return (x>20.0f)? x : log1pf(__expf(x)); }

// ======= shared record recompute (includes gather + in-proj) ==========
// BCt[t][n] = {B,C}, row stride 18 float2 = 144B (16B-aligned rows -> float4 reads)
struct alignas(16) RecSmem {
  float  xi[16][68];      // 4352 B (aliased as y after conv)
  float  xcs[16][68];     // 4352 B
  float  x8h[8][68];      // 2176 B
  float  zsh[16][68];     // 4352 B (k5 only; stride 68 = conflict-free)
  float2 dldu[16][65];    // 8320 B {delta, delta*xc}
  float2 BCt[64][18];     // 9216 B {B, C} transposed
  float  dtv[64];         // 256 B
  float  xp[564];         // 33 rows, stride 17 (2256 B)
  float  iw[256];         // in_w (32,8)
  float  cw[64], cb[16], dtw[16], dtb[16];
};

template<bool WANTZ>
__device__ __forceinline__ void rec_compute(RecSmem& S, int tid, int b, int s, int cis,
    const float* __restrict__ tp, int ibase, int plen,
    const float* __restrict__ t1, const float* __restrict__ t2,
    const float* __restrict__ t3, const float* __restrict__ t4,
    const float* __restrict__ t5,
    const float* __restrict__ in_w, const float* __restrict__ xproj_w,
    const float* __restrict__ conv_w, const float* __restrict__ conv_b,
    const float* __restrict__ dt_w,  const float* __restrict__ dt_b){
  for (int i=tid;i<528;i+=256){ int row=i>>4, col=i&15; S.xp[row*17+col]=xproj_w[i]; }
  S.iw[tid]=in_w[tid];
  if (tid<64) S.cw[tid]=conv_w[tid];
  if (tid<16){ S.cb[tid]=conv_b[tid]; S.dtw[tid]=dt_w[tid]; S.dtb[tid]=dt_b[tid]; }
  if (tid<128){
    int ch=tid>>4, q=tid&15;
    float4 w = *reinterpret_cast<const float4*>(&tp[ibase + ch*plen + q*4]);
    S.x8h[ch][4+q*4+0]=w.x; S.x8h[ch][4+q*4+1]=w.y;
    S.x8h[ch][4+q*4+2]=w.z; S.x8h[ch][4+q*4+3]=w.w;
  } else if (tid<160){
    int u=tid-128, j=u>>3, c=u&7;
    float v=0.f;
    if (cis>0){
      int p = cis*64 - 4 + j;
      int i2=s, pp=p;
      while (pp >= c_plen[i2]) { pp -= c_plen[i2]; ++i2; }
      const float* hp = (i2==0)?t1:(i2==1)?t2:(i2==2)?t3:(i2==3)?t4:t5;
      v = hp[b*c_bs[i2] + (8*s+c)*c_plen[i2] + pp];
    }
    S.x8h[c][j]=v;
  }
  __syncthreads();
  for (int i=tid;i<1088;i+=256){
    int d=i/68, j=i-d*68;
    float acc=0.f;
    #pragma unroll
    for (int c=0;c<8;c++) acc += S.x8h[c][j]*S.iw[d*8+c];
    S.xi[d][j]=acc;
  }
  if (WANTZ){
    #pragma unroll
    for (int k=0;k<4;k++){
      int i=tid+k*256;
      int dd=i>>6, t=i&63;
      float acc=0.f;
      #pragma unroll
      for (int c=0;c<8;c++) acc += S.x8h[c][t+4]*S.iw[(16+dd)*8+c];
      S.zsh[dd][t]=acc;
    }
  }
  __syncthreads();
  #pragma unroll
  for (int k=0;k<4;k++){
    int idx = tid + k*256;
    int d = idx>>6, t = idx&63;
    float acc = S.cb[d];
    #pragma unroll
    for (int kk=0;kk<4;kk++) acc += S.cw[d*4+kk]*S.xi[d][t+1+kk];
    S.xcs[d][t] = siluf(acc);
  }
  __syncthreads();
  if (tid<64){
    float v=0.f;
    #pragma unroll
    for (int d=0;d<16;d++) v += S.xcs[d][tid]*S.xp[d];
    S.dtv[tid]=v;
  }
  __syncthreads();
  {
    int j = tid & 15;
    int t0 = (tid >> 4) << 2;
    float aB0=0.f,aB1=0.f,aB2=0.f,aB3=0.f;
    float aC0=0.f,aC1=0.f,aC2=0.f,aC3=0.f;
    #pragma unroll
    for (int d=0;d<16;d++){
      float4 x4 = *reinterpret_cast<const float4*>(&S.xcs[d][t0]);
      float wb = S.xp[(1+j)*17+d];
      aB0 += x4.x*wb; aB1 += x4.y*wb; aB2 += x4.z*wb; aB3 += x4.w*wb;
      if (WANTZ){
        float wc = S.xp[(17+j)*17+d];
        aC0 += x4.x*wc; aC1 += x4.y*wc; aC2 += x4.z*wc; aC3 += x4.w*wc;
      }
    }
    S.BCt[t0+0][j] = make_float2(aB0, aC0);
    S.BCt[t0+1][j] = make_float2(aB1, aC1);
    S.BCt[t0+2][j] = make_float2(aB2, aC2);
    S.BCt[t0+3][j] = make_float2(aB3, aC3);
  }
  #pragma unroll
  for (int k=0;k<4;k++){
    int idx = tid + k*256;
    int d = idx>>6, t = idx&63;
    float del = softplusf(S.dtv[t]*S.dtw[d]+S.dtb[d]);
    S.dldu[d][t] = make_float2(del, del*S.xcs[d][t]);
  }
  __syncthreads();
}

// ---------------- K3: fused gather+in-proj+record + phase A (P,S) ---------
// scan: 128 threads, thread=(d,g), h[2]/P[2] in registers
__global__ void __launch_bounds__(256,5)
k3_scanA(const float* __restrict__ t1, const float* __restrict__ t2,
         const float* __restrict__ t3, const float* __restrict__ t4,
         const float* __restrict__ t5,
         const float* __restrict__ in_w, const float* __restrict__ xproj_w,
         const float* __restrict__ conv_w, const float* __restrict__ conv_b,
         const float* __restrict__ dt_w, const float* __restrict__ dt_b,
         const float* __restrict__ Alog){
  __shared__ RecSmem S;
  int blk = blockIdx.x;
  int b = blk / TOTC, cg = blk % TOTC;
  int s = (cg>=341)+(cg>=426)+(cg>=447);
  int cis = cg - c_CB[s];
  int tid = threadIdx.x;
  int ti = s, pp = cis*64;
  while (pp >= c_plen[ti]) { pp -= c_plen[ti]; ++ti; }
  const float* tp = (ti==0)?t1:(ti==1)?t2:(ti==2)?t3:(ti==3)?t4:t5;
  int ibase = b*c_bs[ti] + (8*s)*c_plen[ti] + pp;
  rec_compute<false>(S, tid, b, s, cis, tp, ibase, c_plen[ti],
                     t1,t2,t3,t4,t5, in_w, xproj_w, conv_w, conv_b, dt_w, dt_b);
  if (tid < 128){
    int d = tid>>3, g = tid&7;
    float2 al = *reinterpret_cast<const float2*>(&Alog[d*16 + 2*g]);
    const float L2E = 1.4426950408889634f;
    float ac0=-__expf(al.x)*L2E, ac1=-__expf(al.y)*L2E;
    float h0=0.f,h1=0.f,P0=1.f,P1=1.f;
    #pragma unroll 4
    for (int t=0;t<64;t++){
      float2 du = S.dldu[d][t];
      float4 bc = *reinterpret_cast<const float4*>(&S.BCt[t][2*g]);  // B0,C0,B1,C1
      float a0=exp2f(du.x*ac0), a1=exp2f(du.x*ac1);
      h0 = a0*h0 + du.y*bc.x;  P0 *= a0;
      h1 = a1*h1 + du.y*bc.z;  P1 *= a1;
    }
    int idx = (b*TOTC+cg)*256 + d*16 + 2*g;
    *reinterpret_cast<float2*>(&g_P[idx]) = make_float2(P0,P1);
    *reinterpret_cast<float2*>(&g_S[idx]) = make_float2(h0,h1);
  }
}

// ---------------- K4: chunk-prefix scan, software-pipelined ----------------
__global__ void k4_chunk(){
  constexpr int U = 16;
  int b = blockIdx.x >> 2, s = blockIdx.x & 3;
  int tid = threadIdx.x;
  int base = (b*TOTC + c_CB[s])*256 + tid;
  int nc = c_NC[s];
  int nbatch = (nc + U - 1)/U;
  float PA[U],SA[U],PB[U],SB[U];
  #pragma unroll
  for (int u=0;u<U;u++){
    if (u<nc){ int idx=base+u*256; PA[u]=g_P[idx]; SA[u]=g_S[idx]; }
    else { PA[u]=1.f; SA[u]=0.f; }
  }
  float H=0.f;
  for (int bi=0; bi<nbatch; bi+=2){
    if (bi+1<nbatch){
      #pragma unroll
      for (int u=0;u<U;u++){
        int c=(bi+1)*U+u;
        if (c<nc){ int idx=base+c*256; PB[u]=g_P[idx]; SB[u]=g_S[idx]; }
        else { PB[u]=1.f; SB[u]=0.f; }
      }
    }
    #pragma unroll
    for (int u=0;u<U;u++){
      int c=bi*U+u;
      if (c<nc){ g_H[base+c*256]=H; H = PA[u]*H + SA[u]; }
    }
    if (bi+2<nbatch){
      #pragma unroll
      for (int u=0;u<U;u++){
        int c=(bi+2)*U+u;
        if (c<nc){ int idx=base+c*256; PA[u]=g_P[idx]; SA[u]=g_S[idx]; }
        else { PA[u]=1.f; SA[u]=0.f; }
      }
    }
    if (bi+1<nbatch){
      #pragma unroll
      for (int u=0;u<U;u++){
        int c=(bi+1)*U+u;
        if (c<nc){ g_H[base+c*256]=H; H = PB[u]*H + SB[u]; }
      }
    }
  }
}

// ---------------- K5: fused recompute + phase C + epilogue + scatter -------
struct alignas(16) K5Smem {
  RecSmem R;
  float ow[128], pwm[64], pbv[8], gv[8], nbvv[8], Dvv[16];
  float skip; float pad3[3];
};

__global__ void __launch_bounds__(256,5)
k5_scanC(const float* __restrict__ t1, const float* __restrict__ t2,
         const float* __restrict__ t3, const float* __restrict__ t4,
         const float* __restrict__ t5,
         const float* __restrict__ in_w, const float* __restrict__ xproj_w,
         const float* __restrict__ conv_w, const float* __restrict__ conv_b,
         const float* __restrict__ dt_w, const float* __restrict__ dt_b,
         const float* __restrict__ Alog,
         const float* __restrict__ out_w, const float* __restrict__ Dv,
         const float* __restrict__ ng_, const float* __restrict__ nbv,
         const float* __restrict__ pw, const float* __restrict__ pb,
         const float* __restrict__ skipp, float* __restrict__ out){
  __shared__ K5Smem S;
  int blk = blockIdx.x;
  int b = blk / TOTC, cg = blk % TOTC;
  int s = (cg>=341)+(cg>=426)+(cg>=447);
  int cis = cg - c_CB[s];
  int tid = threadIdx.x;
  int ti = s, pp = cis*64;
  while (pp >= c_plen[ti]) { pp -= c_plen[ti]; ++ti; }
  const float* tp = (ti==0)?t1:(ti==1)?t2:(ti==2)?t3:(ti==3)?t4:t5;
  int ibase = b*c_bs[ti] + (8*s)*c_plen[ti] + pp;
  if (tid<128) S.ow[tid]=out_w[tid];
  else {
    int u = tid-128;
    if (u<64) S.pwm[u]=pw[u];
    else if (u<72) S.pbv[u-64]=pb[u-64];
    else if (u<80) S.gv[u-72]=ng_[u-72];
    else if (u<88) S.nbvv[u-80]=nbv[u-80];
    else if (u<104) S.Dvv[u-88]=Dv[u-88];
    else if (u==104) S.skip = skipp[0];
  }
  rec_compute<true>(S.R, tid, b, s, cis, tp, ibase, c_plen[ti],
                    t1,t2,t3,t4,t5, in_w, xproj_w, conv_w, conv_b, dt_w, dt_b);
  float (*ysh)[68] = reinterpret_cast<float (*)[68]>(S.R.xi);  // xi dead after conv
  if (tid < 128){
    int d = tid>>3, g = tid&7;
    float2 al = *reinterpret_cast<const float2*>(&Alog[d*16 + 2*g]);
    const float L2E = 1.4426950408889634f;
    float ac0=-__expf(al.x)*L2E, ac1=-__expf(al.y)*L2E;
    int hidx = (b*TOTC+cg)*256 + d*16 + 2*g;
    float2 h2 = *reinterpret_cast<const float2*>(&g_H[hidx]);
    float h0=h2.x, h1=h2.y;
    #pragma unroll 4
    for (int t=0;t<64;t++){
      float2 du = S.R.dldu[d][t];
      float4 bc = *reinterpret_cast<const float4*>(&S.R.BCt[t][2*g]); // B0,C0,B1,C1
      float a0=exp2f(du.x*ac0), a1=exp2f(du.x*ac1);
      h0 = a0*h0 + du.y*bc.x;
      h1 = a1*h1 + du.y*bc.z;
      float pr = h0*bc.y + h1*bc.w;
      pr += __shfl_xor_sync(0xffffffffu, pr, 1);
      pr += __shfl_xor_sync(0xffffffffu, pr, 2);
      pr += __shfl_xor_sync(0xffffffffu, pr, 4);
      if (g==0) ysh[d][t]=pr;
    }
  }
  __syncthreads();
  // ---- epilogue on 256 threads: thread=(t, quarter q), q covers dd=q*4..q*4+3
  {
    int t = tid>>2, q = tid&3;
    float yf[4];
    #pragma unroll
    for (int i=0;i<4;i++){
      int dd = q*4+i;
      float z = S.R.zsh[dd][t];
      yf[i] = (ysh[dd][t] + S.R.xcs[dd][t]*S.Dvv[dd]) * siluf(z);
    }
    float o[8];
    #pragma unroll
    for (int ch=0;ch<8;ch++){
      float4 w4 = *reinterpret_cast<const float4*>(&S.ow[ch*16+q*4]);
      float acc = yf[0]*w4.x + yf[1]*w4.y + yf[2]*w4.z + yf[3]*w4.w;
      acc += __shfl_xor_sync(0xffffffffu, acc, 1);
      acc += __shfl_xor_sync(0xffffffffu, acc, 2);
      o[ch] = acc;
    }
    if (q==0){
      float mu=0.f;
      #pragma unroll
      for (int ch=0;ch<8;ch++){ o[ch] += S.skip * S.R.x8h[ch][t+4]; mu += o[ch]; }
      mu *= 0.125f;
      float var=0.f;
      #pragma unroll
      for (int ch=0;ch<8;ch++){ float dv=o[ch]-mu; var += dv*dv; }
      var *= 0.125f;
      float rs = rsqrtf(var + 1e-5f);
      float ln[8];
      #pragma unroll
      for (int ch=0;ch<8;ch++) ln[ch] = (o[ch]-mu)*rs*S.gv[ch] + S.nbvv[ch];
      int base = c_obase[ti] + ibase + t;
      #pragma unroll
      for (int j=0;j<8;j++){
        float acc = S.pbv[j];
        #pragma unroll
        for (int ch=0;ch<8;ch++) acc += ln[ch]*S.pwm[j*8+ch];
        out[base + j*c_plen[ti]] = acc;
      }
    }
  }
}

// ---------------- K6: whole m1 path, register-blocked scan -----------------
__global__ void __launch_bounds__(512)
k6_m1(const float* __restrict__ t5, const float* __restrict__ in_w,
      const float* __restrict__ conv_w, const float* __restrict__ conv_b,
      const float* __restrict__ xproj_w, const float* __restrict__ dt_w,
      const float* __restrict__ dt_b, const float* __restrict__ Alog,
      const float* __restrict__ Dv, const float* __restrict__ out_w,
      const float* __restrict__ ng, const float* __restrict__ nbv,
      const float* __restrict__ pw, const float* __restrict__ pb,
      const float* __restrict__ skipp, float* __restrict__ out){
  __shared__ float s_iw[1024];              // in_w (64,16)
  __shared__ float s_x[64][17];
  __shared__ float s_xi[64][33];            // xi, then delta
  __shared__ float s_xc[64][33];
  __shared__ __align__(16) float s_B[64][20];
  __shared__ __align__(16) float s_C[64][20];
  __shared__ float s_dt[64];
  __shared__ float s_y[64][33];
  int b = blockIdx.x, tid = threadIdx.x;
  for (int i=tid;i<1024;i+=512) s_iw[i]=in_w[i];
  for (int i=tid;i<1024;i+=512){
    int t=i>>4, c=i&15;
    s_x[t][c] = t5[b*3072 + (32+c)*64 + t];
  }
  __syncthreads();
  for (int i=tid;i<2048;i+=512){     // in-proj xi (rows 0..31 of in_w)
    int t=i>>5, j=i&31;
    float v=0.f;
    #pragma unroll
    for (int c=0;c<16;c++) v += s_x[t][c]*s_iw[j*16+c];
    s_xi[t][j]=v;
  }
  __syncthreads();
  for (int i=tid;i<2048;i+=512){     // conv + silu
    int t=i>>5, d=i&31;
    float acc = conv_b[d];
    #pragma unroll
    for (int k=0;k<4;k++){
      int tt = t-3+k;
      if (tt>=0) acc += conv_w[d*4+k]*s_xi[tt][d];
    }
    s_xc[t][d] = siluf(acc);
  }
  __syncthreads();
  for (int i=tid;i<64*33;i+=512){    // x-proj
    int t=i/33, j=i%33;
    float v=0.f;
    #pragma unroll
    for (int d=0;d<32;d++) v += s_xc[t][d]*xproj_w[j*32+d];
    if (j==0) s_dt[t]=v;
    else if (j<17) s_B[t][j-1]=v;
    else s_C[t][j-17]=v;
  }
  __syncthreads();
  for (int i=tid;i<2048;i+=512){     // delta (overwrites s_xi)
    int t=i>>5, d=i&31;
    s_xi[t][d] = softplusf(s_dt[t]*dt_w[d] + dt_b[d]);
  }
  __syncthreads();
  if (tid < 128){                    // scan: thread=(d,ng), h[4] in regs
    int d=tid>>2, ngi=tid&3;
    float4 al = *reinterpret_cast<const float4*>(&Alog[d*16 + 4*ngi]);
    const float L2E = 1.4426950408889634f;
    float ac0=-__expf(al.x)*L2E, ac1=-__expf(al.y)*L2E,
          ac2=-__expf(al.z)*L2E, ac3=-__expf(al.w)*L2E;
    float h0=0.f,h1=0.f,h2=0.f,h3=0.f;
    #pragma unroll 4
    for (int t=0;t<64;t++){
      float dl = s_xi[t][d];
      float du = dl*s_xc[t][d];
      float4 Bv = *reinterpret_cast<const float4*>(&s_B[t][4*ngi]);
      float4 Cv = *reinterpret_cast<const float4*>(&s_C[t][4*ngi]);
      float a0=exp2f(dl*ac0), a1=exp2f(dl*ac1),
            a2=exp2f(dl*ac2), a3=exp2f(dl*ac3);
      h0 = a0*h0 + du*Bv.x;
      h1 = a1*h1 + du*Bv.y;
      h2 = a2*h2 + du*Bv.z;
      h3 = a3*h3 + du*Bv.w;
      float pr = h0*Cv.x + h1*Cv.y + h2*Cv.z + h3*Cv.w;
      pr += __shfl_xor_sync(0xffffffffu, pr, 1);
      pr += __shfl_xor_sync(0xffffffffu, pr, 2);
      if (ngi==0) s_y[t][d]=pr;
    }
  }
  __syncthreads();
  if (tid<64){
    int t=tid;
    float skip = skipp[0];
    float yf[32];
    #pragma unroll
    for (int d=0;d<32;d++){
      float z=0.f;                   // recompute z from staged x + in_w
      #pragma unroll
      for (int c=0;c<16;c++) z += s_x[t][c]*s_iw[(32+d)*16+c];
      yf[d] = (s_y[t][d] + s_xc[t][d]*Dv[d]) * siluf(z);
    }
    float o[16]; float mu=0.f;
    #pragma unroll
    for (int ch=0;ch<16;ch++){
      float acc = skip * s_x[t][ch];
      #pragma unroll
      for (int d=0;d<32;d++) acc += yf[d]*out_w[ch*32+d];
      o[ch]=acc; mu+=acc;
    }
    mu *= (1.0f/16.0f);
    float var=0.f;
    #pragma unroll
    for (int ch=0;ch<16;ch++){ float dv=o[ch]-mu; var+=dv*dv; }
    var *= (1.0f/16.0f);
    float rs = rsqrtf(var+1e-5f);
    float ln[16];
    #pragma unroll
    for (int ch=0;ch<16;ch++) ln[ch] = (o[ch]-mu)*rs*ng[ch]+nbv[ch];
    #pragma unroll
    for (int j=0;j<16;j++){
      float acc = pb[j];
      #pragma unroll
      for (int ch=0;ch<16;ch++) acc += ln[ch]*pw[j*16+ch];
      out[1835008 + b*3072 + (32+j)*64 + t] = acc;
    }
  }
}

// ---------------- launch ----------------
extern "C" void kernel_launch(void* const* d_in, const int* in_sizes, int n_in,
                              void* d_out, int out_size){
  (void)in_sizes; (void)n_in; (void)out_size;
  const float* t1 = (const float*)d_in[0];
  const float* t2 = (const float*)d_in[1];
  const float* t3 = (const float*)d_in[2];
  const float* t4 = (const float*)d_in[3];
  const float* t5 = (const float*)d_in[4];
  float* out = (float*)d_out;

  k3_scanA<<<NB*TOTC, 256>>>(t1,t2,t3,t4,t5,
                             (const float*)d_in[5],(const float*)d_in[8],
                             (const float*)d_in[6],(const float*)d_in[7],
                             (const float*)d_in[9],(const float*)d_in[10],
                             (const float*)d_in[11]);
  k4_chunk<<<32, 256>>>();
  k5_scanC<<<NB*TOTC, 256>>>(t1,t2,t3,t4,t5,
                             (const float*)d_in[5],(const float*)d_in[8],
                             (const float*)d_in[6],(const float*)d_in[7],
                             (const float*)d_in[9],(const float*)d_in[10],
                             (const float*)d_in[11],
                             (const float*)d_in[13],(const float*)d_in[12],
                             (const float*)d_in[23],(const float*)d_in[24],
                             (const float*)d_in[25],(const float*)d_in[26],
                             (const float*)d_in[31], out);
  k6_m1   <<<NB, 512>>>(t5,(const float*)d_in[14],(const float*)d_in[15],
                        (const float*)d_in[16],(const float*)d_in[17],
                        (const float*)d_in[18],(const float*)d_in[19],
                        (const float*)d_in[20],(const float*)d_in[21],
                        (const float*)d_in[22],(const float*)d_in[27],
                        (const float*)d_in[28],(const float*)d_in[29],
                        (const float*)d_in[30],(const float*)d_in[31], out);
}